// round 2
// baseline (speedup 1.0000x reference)
#include <cuda_runtime.h>
#include <cuda_bf16.h>

// EdgeNetwork: per-edge MLP(concat(src,dst,attr)) with 2x LayerNorm+LeakyReLU.
// Strategy: 256-edge tile / 256-thread CTA. Weights in smem (broadcast LDS),
// X gathered coalesced into smem edge-major (stride 145, conflict-free),
// each lane owns one edge end-to-end with f32x2 packed FFMA accumulators.
// NOTE: edge_index arrives as int32 (JAX x64-disabled downgrades the declared
// int64), laid out [2, E]: src = idx[e], dst = idx[E + e].

#define IN_DIM   144
#define HID      64
#define TILE     256
#define NTHREADS 256
#define XSTRIDE  145   // 144 + 1 pad; odd stride -> conflict-free per-lane rows

// smem layout (floats): w1[144*64] | w2[64*64] | prm[512] | xs[256*145]
#define W1_OFF   0
#define W2_OFF   (144*64)            // 9216
#define PRM_OFF  (W2_OFF + 64*64)    // 13312
#define XS_OFF   (PRM_OFF + 512)     // 13824
#define SMEM_FLOATS (XS_OFF + TILE*XSTRIDE)   // 50944
#define SMEM_BYTES  (SMEM_FLOATS * 4)         // 203776

__device__ __forceinline__ unsigned long long pack2(float lo, float hi) {
    unsigned long long r;
    asm("mov.b64 %0, {%1, %2};" : "=l"(r) : "f"(lo), "f"(hi));
    return r;
}
__device__ __forceinline__ void unpack2(unsigned long long v, float& lo, float& hi) {
    asm("mov.b64 {%0, %1}, %2;" : "=f"(lo), "=f"(hi) : "l"(v));
}
#define FFMA2(acc, a, b) \
    asm("fma.rn.f32x2 %0, %1, %2, %0;" : "+l"(acc) : "l"(a), "l"(b))

__global__ __launch_bounds__(NTHREADS, 1)
void edgenet_kernel(const float* __restrict__ nodef,
                    const int* __restrict__ eidx,
                    const float* __restrict__ eattr,
                    const float* __restrict__ W1, const float* __restrict__ B1,
                    const float* __restrict__ G1, const float* __restrict__ BE1,
                    const float* __restrict__ W2, const float* __restrict__ B2,
                    const float* __restrict__ G2, const float* __restrict__ BE2,
                    const float* __restrict__ W3, const float* __restrict__ B3,
                    float* __restrict__ out, int E, int nNodes)
{
    extern __shared__ float smem[];
    float* w1  = smem + W1_OFF;
    float* w2  = smem + W2_OFF;
    float* prm = smem + PRM_OFF;
    float* xs  = smem + XS_OFF;

    const int tid  = threadIdx.x;
    const int lane = tid & 31;
    const int warp = tid >> 5;

    // ---- cooperative weight/param load ----
    for (int i = tid; i < 144*64; i += NTHREADS) w1[i] = W1[i];
    for (int i = tid; i < 64*64;  i += NTHREADS) w2[i] = W2[i];
    if (tid < 64) {
        prm[tid]       = B1[tid];
        prm[64 + tid]  = G1[tid];
        prm[128 + tid] = BE1[tid];
        prm[192 + tid] = B2[tid];
        prm[256 + tid] = G2[tid];
        prm[320 + tid] = BE2[tid];
        prm[384 + tid] = W3[tid];
    }
    if (tid == 0) prm[448] = B3[0];
    __syncthreads();

    // ---- warp-local coalesced gather of 32 edges into smem (edge-major) ----
    const long long eBase = (long long)blockIdx.x * TILE + (long long)warp * 32;
    float* xw = xs + warp * 32 * XSTRIDE;

    const float4* nf4 = (const float4*)nodef;   // node row = 16 float4
    const float4* ea4 = (const float4*)eattr;   // attr row = 4 float4

    // src (k 0..63) and dst (k 64..127): 16 lanes per row -> 2 cache lines/row
    #pragma unroll
    for (int half = 0; half < 2; ++half) {
        #pragma unroll
        for (int i = 0; i < 16; ++i) {
            int elocal = i * 2 + (lane >> 4);
            int f4     = lane & 15;
            long long eg = eBase + elocal;
            int node = 0;
            if (eg < (long long)E)
                node = (half ? eidx[(long long)E + eg] : eidx[eg]);
            // safety clamp: wrong-answer beats illegal-access if dtype theory is off
            if (node < 0) node = 0;
            if (node >= nNodes) node = nNodes - 1;
            float4 v = nf4[(long long)node * 16 + f4];
            float* d = xw + elocal * XSTRIDE + half * 64 + f4 * 4;
            d[0] = v.x; d[1] = v.y; d[2] = v.z; d[3] = v.w;
        }
    }
    // edge_attr (k 128..143)
    #pragma unroll
    for (int i = 0; i < 4; ++i) {
        int elocal = i * 8 + (lane >> 2);
        int f4     = lane & 3;
        long long eg = eBase + elocal;
        float4 v = make_float4(0.f, 0.f, 0.f, 0.f);
        if (eg < (long long)E) v = ea4[eg * 4 + f4];
        float* d = xw + elocal * XSTRIDE + 128 + f4 * 4;
        d[0] = v.x; d[1] = v.y; d[2] = v.z; d[3] = v.w;
    }
    __syncwarp();

    // ---- lane owns edge eBase+lane; x row is private ----
    float* xrow = xw + lane * XSTRIDE;

    unsigned long long acc[32];
    float h[64];

    // ================= Layer 1: 144 -> 64 =================
    #pragma unroll
    for (int p = 0; p < 32; ++p) acc[p] = 0ull;

    #pragma unroll 2
    for (int k = 0; k < IN_DIM; ++k) {
        float xk = xrow[k];
        unsigned long long xp = pack2(xk, xk);
        const ulonglong2* wr = reinterpret_cast<const ulonglong2*>(w1 + k * 64);
        #pragma unroll
        for (int q = 0; q < 16; ++q) {
            ulonglong2 wv = wr[q];
            FFMA2(acc[2*q],     xp, wv.x);
            FFMA2(acc[2*q + 1], xp, wv.y);
        }
    }

    // LayerNorm 1 + LeakyReLU (fully in-register, per-lane)
    {
        #pragma unroll
        for (int p = 0; p < 32; ++p) {
            float lo, hi;
            unpack2(acc[p], lo, hi);
            h[2*p]     = lo + prm[2*p];
            h[2*p + 1] = hi + prm[2*p + 1];
        }
        float s = 0.f, ss = 0.f;
        #pragma unroll
        for (int j = 0; j < 64; ++j) { s += h[j]; ss += h[j] * h[j]; }
        float mu   = s * (1.0f / 64.0f);
        float var  = ss * (1.0f / 64.0f) - mu * mu;
        float rstd = rsqrtf(var + 1e-5f);
        #pragma unroll
        for (int j = 0; j < 64; ++j) {
            float y = (h[j] - mu) * rstd * prm[64 + j] + prm[128 + j];
            y = (y < 0.f) ? 0.1f * y : y;
            xrow[j] = y;   // layer-2 input back to the private smem row
        }
    }

    // ================= Layer 2: 64 -> 64 =================
    #pragma unroll
    for (int p = 0; p < 32; ++p) acc[p] = 0ull;

    #pragma unroll 2
    for (int k = 0; k < HID; ++k) {
        float xk = xrow[k];
        unsigned long long xp = pack2(xk, xk);
        const ulonglong2* wr = reinterpret_cast<const ulonglong2*>(w2 + k * 64);
        #pragma unroll
        for (int q = 0; q < 16; ++q) {
            ulonglong2 wv = wr[q];
            FFMA2(acc[2*q],     xp, wv.x);
            FFMA2(acc[2*q + 1], xp, wv.y);
        }
    }

    // LayerNorm 2 + LeakyReLU (result stays in h[])
    {
        #pragma unroll
        for (int p = 0; p < 32; ++p) {
            float lo, hi;
            unpack2(acc[p], lo, hi);
            h[2*p]     = lo + prm[192 + 2*p];
            h[2*p + 1] = hi + prm[192 + 2*p + 1];
        }
        float s = 0.f, ss = 0.f;
        #pragma unroll
        for (int j = 0; j < 64; ++j) { s += h[j]; ss += h[j] * h[j]; }
        float mu   = s * (1.0f / 64.0f);
        float var  = ss * (1.0f / 64.0f) - mu * mu;
        float rstd = rsqrtf(var + 1e-5f);
        #pragma unroll
        for (int j = 0; j < 64; ++j) {
            float y = (h[j] - mu) * rstd * prm[256 + j] + prm[320 + j];
            h[j] = (y < 0.f) ? 0.1f * y : y;
        }
    }

    // ================= Layer 3: 64 -> 1 =================
    float r = prm[448];
    #pragma unroll
    for (int j = 0; j < 64; ++j) r += h[j] * prm[384 + j];

    long long e = eBase + lane;
    if (e < (long long)E) out[e] = r;
}

extern "C" void kernel_launch(void* const* d_in, const int* in_sizes, int n_in,
                              void* d_out, int out_size)
{
    const float* nodef = (const float*)d_in[0];
    const int*   eidx  = (const int*)d_in[1];   // int32 [2, E] (JAX x64-off)
    const float* eattr = (const float*)d_in[2];
    const float* W1  = (const float*)d_in[3];
    const float* B1  = (const float*)d_in[4];
    const float* G1  = (const float*)d_in[5];
    const float* BE1 = (const float*)d_in[6];
    const float* W2  = (const float*)d_in[7];
    const float* B2  = (const float*)d_in[8];
    const float* G2  = (const float*)d_in[9];
    const float* BE2 = (const float*)d_in[10];
    const float* W3  = (const float*)d_in[11];
    const float* B3  = (const float*)d_in[12];
    float* out = (float*)d_out;

    int E      = out_size;             // one logit per edge
    int nNodes = in_sizes[0] / 64;     // node_features is (n_nodes, 64)
    int grid   = (E + TILE - 1) / TILE;

    cudaFuncSetAttribute(edgenet_kernel,
                         cudaFuncAttributeMaxDynamicSharedMemorySize, SMEM_BYTES);
    edgenet_kernel<<<grid, NTHREADS, SMEM_BYTES>>>(
        nodef, eidx, eattr, W1, B1, G1, BE1, W2, B2, G2, BE2, W3, B3,
        out, E, nNodes);
}

// round 3
// speedup vs baseline: 1.2873x; 1.2873x over previous
#include <cuda_runtime.h>
#include <cuda_bf16.h>

// EdgeNetwork on GB300 — R3: 2 edges per lane (weight-load amortization).
// L1/shared was 80% (bottleneck); halve LDS-per-FLOP by register-blocking M=2.
// CTA = 256 threads, 512 edges. Layer-1 phased by k-chunk (src/dst/attr) to
// fit the x staging buffer in smem. Layer-3 fused into LN2 epilogue.

#define HID      64
#define EPC      512          // edges per CTA
#define NTHREADS 256
#define XST      65           // x row stride (64 + 1 pad)

// smem floats: w1[144*64] | w2[64*64] | prm[512] | xbuf[512*65]
#define W1_OFF   0
#define W2_OFF   (144*64)                 // 9216
#define PRM_OFF  (W2_OFF + 64*64)         // 13312
#define XB_OFF   (PRM_OFF + 512)          // 13824
#define SMEM_FLOATS (XB_OFF + EPC*XST)    // 47104
#define SMEM_BYTES  (SMEM_FLOATS * 4)     // 188416

__device__ __forceinline__ unsigned long long pack2(float lo, float hi) {
    unsigned long long r;
    asm("mov.b64 %0, {%1, %2};" : "=l"(r) : "f"(lo), "f"(hi));
    return r;
}
__device__ __forceinline__ void unpack2(unsigned long long v, float& lo, float& hi) {
    asm("mov.b64 {%0, %1}, %2;" : "=f"(lo), "=f"(hi) : "l"(v));
}
#define FFMA2(acc, a, b) \
    asm("fma.rn.f32x2 %0, %1, %2, %0;" : "+l"(acc) : "l"(a), "l"(b))

__global__ __launch_bounds__(NTHREADS, 1)
void edgenet_kernel(const float* __restrict__ nodef,
                    const int* __restrict__ eidx,
                    const float* __restrict__ eattr,
                    const float* __restrict__ W1, const float* __restrict__ B1,
                    const float* __restrict__ G1, const float* __restrict__ BE1,
                    const float* __restrict__ W2, const float* __restrict__ B2,
                    const float* __restrict__ G2, const float* __restrict__ BE2,
                    const float* __restrict__ W3, const float* __restrict__ B3,
                    float* __restrict__ out, int E, int nNodes)
{
    extern __shared__ float smem[];
    float* w1   = smem + W1_OFF;
    float* w2   = smem + W2_OFF;
    float* prm  = smem + PRM_OFF;
    float* xbuf = smem + XB_OFF;

    const int tid  = threadIdx.x;
    const int lane = tid & 31;
    const int warp = tid >> 5;

    // ---- cooperative weight/param load ----
    for (int i = tid; i < 144*64; i += NTHREADS) w1[i] = W1[i];
    for (int i = tid; i < 64*64;  i += NTHREADS) w2[i] = W2[i];
    if (tid < 64) {
        prm[tid]       = B1[tid];
        prm[64 + tid]  = G1[tid];
        prm[128 + tid] = BE1[tid];
        prm[192 + tid] = B2[tid];
        prm[256 + tid] = G2[tid];
        prm[320 + tid] = BE2[tid];
        prm[384 + tid] = W3[tid];
    }
    if (tid == 0) prm[448] = B3[0];
    __syncthreads();

    // ---- warp owns 64 consecutive edges; lane owns 2 (lane, lane+32) ----
    const long long eBase = (long long)blockIdx.x * EPC + (long long)warp * 64;
    float* xw = xbuf + warp * 64 * XST;           // this warp's 64 x-rows
    float* xlo = xw + lane * XST;                 // edge eBase+lane
    float* xhi = xw + (lane + 32) * XST;          // edge eBase+lane+32

    const float4* nf4 = (const float4*)nodef;
    const float4* ea4 = (const float4*)eattr;

    unsigned long long aLo[32], aHi[32];
    #pragma unroll
    for (int p = 0; p < 32; ++p) { aLo[p] = 0ull; aHi[p] = 0ull; }

    // ============ Layer 1 (144 -> 64), phased by k-chunk ============
    #pragma unroll
    for (int phase = 0; phase < 2; ++phase) {     // 0: src (k0-63), 1: dst (k64-127)
        // gather 64 node rows, coalesced: 16 lanes x float4 per row
        #pragma unroll
        for (int i = 0; i < 32; ++i) {
            int elocal = i * 2 + (lane >> 4);
            int f4     = lane & 15;
            long long eg = eBase + elocal;
            int node = 0;
            if (eg < (long long)E)
                node = (phase ? eidx[(long long)E + eg] : eidx[eg]);
            if (node < 0) node = 0;
            if (node >= nNodes) node = nNodes - 1;
            float4 v = nf4[(long long)node * 16 + f4];
            float* d = xw + elocal * XST + f4 * 4;
            d[0] = v.x; d[1] = v.y; d[2] = v.z; d[3] = v.w;
        }
        __syncwarp();

        const float* wbase = w1 + phase * 64 * 64;
        #pragma unroll 2
        for (int kk = 0; kk < 64; ++kk) {
            float xl = xlo[kk], xh = xhi[kk];
            unsigned long long xpl = pack2(xl, xl);
            unsigned long long xph = pack2(xh, xh);
            const ulonglong2* wr = reinterpret_cast<const ulonglong2*>(wbase + kk * 64);
            #pragma unroll
            for (int q = 0; q < 16; ++q) {
                ulonglong2 wv = wr[q];
                FFMA2(aLo[2*q],     xpl, wv.x);
                FFMA2(aLo[2*q + 1], xpl, wv.y);
                FFMA2(aHi[2*q],     xph, wv.x);
                FFMA2(aHi[2*q + 1], xph, wv.y);
            }
        }
        __syncwarp();
    }
    {   // phase 2: edge_attr (k128-143)
        #pragma unroll
        for (int i = 0; i < 8; ++i) {
            int elocal = i * 8 + (lane >> 2);
            int f4     = lane & 3;
            long long eg = eBase + elocal;
            float4 v = make_float4(0.f, 0.f, 0.f, 0.f);
            if (eg < (long long)E) v = ea4[eg * 4 + f4];
            float* d = xw + elocal * XST + f4 * 4;
            d[0] = v.x; d[1] = v.y; d[2] = v.z; d[3] = v.w;
        }
        __syncwarp();

        const float* wbase = w1 + 128 * 64;
        #pragma unroll
        for (int kk = 0; kk < 16; ++kk) {
            float xl = xlo[kk], xh = xhi[kk];
            unsigned long long xpl = pack2(xl, xl);
            unsigned long long xph = pack2(xh, xh);
            const ulonglong2* wr = reinterpret_cast<const ulonglong2*>(wbase + kk * 64);
            #pragma unroll
            for (int q = 0; q < 16; ++q) {
                ulonglong2 wv = wr[q];
                FFMA2(aLo[2*q],     xpl, wv.x);
                FFMA2(aLo[2*q + 1], xpl, wv.y);
                FFMA2(aHi[2*q],     xph, wv.x);
                FFMA2(aHi[2*q + 1], xph, wv.y);
            }
        }
        __syncwarp();
    }

    // ---- LN1 + LeakyReLU: two passes over live accumulators, write to smem row
    {
        float sL = 0.f, ssL = 0.f, sH = 0.f, ssH = 0.f;
        #pragma unroll
        for (int p = 0; p < 32; ++p) {
            float lo, hi;
            unpack2(aLo[p], lo, hi);
            lo += prm[2*p]; hi += prm[2*p + 1];
            sL += lo + hi; ssL += lo*lo + hi*hi;
            unpack2(aHi[p], lo, hi);
            lo += prm[2*p]; hi += prm[2*p + 1];
            sH += lo + hi; ssH += lo*lo + hi*hi;
        }
        float muL  = sL * (1.f/64.f), muH = sH * (1.f/64.f);
        float rsL  = rsqrtf(ssL * (1.f/64.f) - muL*muL + 1e-5f);
        float rsH  = rsqrtf(ssH * (1.f/64.f) - muH*muH + 1e-5f);
        #pragma unroll
        for (int p = 0; p < 32; ++p) {
            float lo, hi;
            unpack2(aLo[p], lo, hi);
            {
                float y0 = (lo + prm[2*p]   - muL) * rsL * prm[64 + 2*p]   + prm[128 + 2*p];
                float y1 = (hi + prm[2*p+1] - muL) * rsL * prm[64 + 2*p+1] + prm[128 + 2*p+1];
                y0 = (y0 < 0.f) ? 0.1f * y0 : y0;
                y1 = (y1 < 0.f) ? 0.1f * y1 : y1;
                xlo[2*p] = y0; xlo[2*p + 1] = y1;
            }
            unpack2(aHi[p], lo, hi);
            {
                float y0 = (lo + prm[2*p]   - muH) * rsH * prm[64 + 2*p]   + prm[128 + 2*p];
                float y1 = (hi + prm[2*p+1] - muH) * rsH * prm[64 + 2*p+1] + prm[128 + 2*p+1];
                y0 = (y0 < 0.f) ? 0.1f * y0 : y0;
                y1 = (y1 < 0.f) ? 0.1f * y1 : y1;
                xhi[2*p] = y0; xhi[2*p + 1] = y1;
            }
            aLo[p] = 0ull; aHi[p] = 0ull;
        }
    }

    // ============ Layer 2 (64 -> 64) ============
    #pragma unroll 2
    for (int kk = 0; kk < HID; ++kk) {
        float xl = xlo[kk], xh = xhi[kk];
        unsigned long long xpl = pack2(xl, xl);
        unsigned long long xph = pack2(xh, xh);
        const ulonglong2* wr = reinterpret_cast<const ulonglong2*>(w2 + kk * 64);
        #pragma unroll
        for (int q = 0; q < 16; ++q) {
            ulonglong2 wv = wr[q];
            FFMA2(aLo[2*q],     xpl, wv.x);
            FFMA2(aLo[2*q + 1], xpl, wv.y);
            FFMA2(aHi[2*q],     xph, wv.x);
            FFMA2(aHi[2*q + 1], xph, wv.y);
        }
    }

    // ---- LN2 + LeakyReLU + fused layer-3 dot ----
    {
        float sL = 0.f, ssL = 0.f, sH = 0.f, ssH = 0.f;
        #pragma unroll
        for (int p = 0; p < 32; ++p) {
            float lo, hi;
            unpack2(aLo[p], lo, hi);
            lo += prm[192 + 2*p]; hi += prm[192 + 2*p + 1];
            sL += lo + hi; ssL += lo*lo + hi*hi;
            unpack2(aHi[p], lo, hi);
            lo += prm[192 + 2*p]; hi += prm[192 + 2*p + 1];
            sH += lo + hi; ssH += lo*lo + hi*hi;
        }
        float muL = sL * (1.f/64.f), muH = sH * (1.f/64.f);
        float rsL = rsqrtf(ssL * (1.f/64.f) - muL*muL + 1e-5f);
        float rsH = rsqrtf(ssH * (1.f/64.f) - muH*muH + 1e-5f);

        float rL = prm[448], rH = prm[448];
        #pragma unroll
        for (int p = 0; p < 32; ++p) {
            float lo, hi;
            unpack2(aLo[p], lo, hi);
            {
                float y0 = (lo + prm[192+2*p]   - muL) * rsL * prm[256+2*p]   + prm[320+2*p];
                float y1 = (hi + prm[192+2*p+1] - muL) * rsL * prm[256+2*p+1] + prm[320+2*p+1];
                y0 = (y0 < 0.f) ? 0.1f * y0 : y0;
                y1 = (y1 < 0.f) ? 0.1f * y1 : y1;
                rL += y0 * prm[384 + 2*p] + y1 * prm[384 + 2*p + 1];
            }
            unpack2(aHi[p], lo, hi);
            {
                float y0 = (lo + prm[192+2*p]   - muH) * rsH * prm[256+2*p]   + prm[320+2*p];
                float y1 = (hi + prm[192+2*p+1] - muH) * rsH * prm[256+2*p+1] + prm[320+2*p+1];
                y0 = (y0 < 0.f) ? 0.1f * y0 : y0;
                y1 = (y1 < 0.f) ? 0.1f * y1 : y1;
                rH += y0 * prm[384 + 2*p] + y1 * prm[384 + 2*p + 1];
            }
        }

        long long eLo = eBase + lane;
        long long eHi = eBase + lane + 32;
        if (eLo < (long long)E) out[eLo] = rL;
        if (eHi < (long long)E) out[eHi] = rH;
    }
}

extern "C" void kernel_launch(void* const* d_in, const int* in_sizes, int n_in,
                              void* d_out, int out_size)
{
    const float* nodef = (const float*)d_in[0];
    const int*   eidx  = (const int*)d_in[1];   // int32 [2, E]
    const float* eattr = (const float*)d_in[2];
    const float* W1  = (const float*)d_in[3];
    const float* B1  = (const float*)d_in[4];
    const float* G1  = (const float*)d_in[5];
    const float* BE1 = (const float*)d_in[6];
    const float* W2  = (const float*)d_in[7];
    const float* B2  = (const float*)d_in[8];
    const float* G2  = (const float*)d_in[9];
    const float* BE2 = (const float*)d_in[10];
    const float* W3  = (const float*)d_in[11];
    const float* B3  = (const float*)d_in[12];
    float* out = (float*)d_out;

    int E      = out_size;
    int nNodes = in_sizes[0] / 64;
    int grid   = (E + EPC - 1) / EPC;

    cudaFuncSetAttribute(edgenet_kernel,
                         cudaFuncAttributeMaxDynamicSharedMemorySize, SMEM_BYTES);
    edgenet_kernel<<<grid, NTHREADS, SMEM_BYTES>>>(
        nodef, eidx, eattr, W1, B1, G1, BE1, W2, B2, G2, BE2, W3, B3,
        out, E, nNodes);
}

// round 6
// speedup vs baseline: 1.8392x; 1.4288x over previous
#include <cuda_runtime.h>
#include <cstdint>

// EdgeNetwork R6 — warp-level mma.sync tf32 (tensor pipe without tcgen05,
// which ptxas rejects for the harness's compute_103 target).
// CTA = 128 edges, 256 thr. Warp (rg,cg) owns rows rg*32+..32, cols cg*32+..32.
// X tf32 row-major stride 164 (bank-conflict-free fragment reads),
// W k-major stride 72, H stride 68. LN via shfl + smem cg-pair exchange.

#define XS1 164   // X row stride (words); 164 % 32 == 4
#define WS  72    // W row stride; 72 % 32 == 8
#define HS  68    // H row stride; 68 % 32 == 4

// smem word offsets
#define X_OFF   0
#define W1_OFF  (128 * XS1)                  // 20992
#define W2_OFF  (W1_OFF + 144 * WS)          // 31360
#define PRM_OFF (W2_OFF + 64 * WS)           // 35968
#define RED_OFF (PRM_OFF + 452)              // 36420 (128 rows x 2 cg x float2)
#define DOT_OFF (RED_OFF + 512)              // 36932 (128 x 2)
#define SMEM_WORDS (DOT_OFF + 256)           // 37188
#define SMEM_BYTES (SMEM_WORDS * 4)          // 148752

__device__ __forceinline__ uint32_t f2tf32(float f) {
    uint32_t r;
    asm("cvt.rna.tf32.f32 %0, %1;" : "=r"(r) : "f"(f));
    return r;
}

#define MMA_TF32(d, a, b0, b1) \
    asm volatile("mma.sync.aligned.m16n8k8.row.col.f32.tf32.tf32.f32 " \
        "{%0,%1,%2,%3}, {%4,%5,%6,%7}, {%8,%9}, {%0,%1,%2,%3};" \
        : "+f"((d)[0]), "+f"((d)[1]), "+f"((d)[2]), "+f"((d)[3]) \
        : "r"((a)[0]), "r"((a)[1]), "r"((a)[2]), "r"((a)[3]), "r"(b0), "r"(b1))

__global__ __launch_bounds__(256, 1)
void edgenet_mma(const float* __restrict__ nodef,
                 const int* __restrict__ eidx,
                 const float* __restrict__ eattr,
                 const float* __restrict__ W1, const float* __restrict__ pB1,
                 const float* __restrict__ G1, const float* __restrict__ BE1,
                 const float* __restrict__ W2, const float* __restrict__ pB2,
                 const float* __restrict__ G2, const float* __restrict__ BE2,
                 const float* __restrict__ W3, const float* __restrict__ pB3,
                 float* __restrict__ out, int E, int nNodes)
{
    extern __shared__ uint32_t smem[];
    uint32_t* Xs  = smem + X_OFF;      // tf32 bits
    uint32_t* W1s = smem + W1_OFF;
    uint32_t* W2s = smem + W2_OFF;
    float*    prm = (float*)(smem + PRM_OFF);
    float2*   red = (float2*)(smem + RED_OFF);
    float*    dot = (float*)(smem + DOT_OFF);

    const int tid  = threadIdx.x;
    const int lane = tid & 31;
    const int wid  = tid >> 5;
    const int rg   = wid >> 1;        // row group: rows rg*32..+31
    const int cg   = wid & 1;         // col group: cols cg*32..+31
    const int qr   = lane >> 2;       // 0..7
    const int qc   = lane & 3;        // 0..3

    // ---- stage weights (transposed to k-major=natural W[k][n]) + params ----
    for (int i = tid; i < 144 * 64; i += 256) {
        int k = i >> 6, n = i & 63;
        W1s[k * WS + n] = f2tf32(W1[i]);
    }
    for (int i = tid; i < 64 * 64; i += 256) {
        int k = i >> 6, n = i & 63;
        W2s[k * WS + n] = f2tf32(W2[i]);
    }
    if (tid < 64) {
        prm[tid]       = pB1[tid];
        prm[64 + tid]  = G1[tid];
        prm[128 + tid] = BE1[tid];
        prm[192 + tid] = pB2[tid];
        prm[256 + tid] = G2[tid];
        prm[320 + tid] = BE2[tid];
        prm[384 + tid] = W3[tid];
    }
    if (tid == 0) prm[448] = pB3[0];

    // ---- gather X (tf32) into rows [128][164] ----
    const int eBase = blockIdx.x * 128;
    const float4* nf4 = (const float4*)nodef;
    const float4* ea4 = (const float4*)eattr;

    #pragma unroll
    for (int half = 0; half < 2; ++half) {
        #pragma unroll
        for (int i = 0; i < 8; ++i) {
            int r  = wid * 16 + i * 2 + (lane >> 4);
            int f4 = lane & 15;
            int eg = eBase + r;
            int node = 0;
            if (eg < E) node = half ? eidx[(size_t)E + eg] : eidx[eg];
            if (node < 0) node = 0;
            if (node >= nNodes) node = nNodes - 1;
            float4 v = nf4[(size_t)node * 16 + f4];
            uint4 t = make_uint4(f2tf32(v.x), f2tf32(v.y), f2tf32(v.z), f2tf32(v.w));
            *(uint4*)(Xs + r * XS1 + half * 64 + f4 * 4) = t;
        }
    }
    #pragma unroll
    for (int t2 = 0; t2 < 2; ++t2) {
        int j = tid + t2 * 256;
        int r = j >> 2, f4 = j & 3;
        int eg = eBase + r;
        float4 v = make_float4(0.f, 0.f, 0.f, 0.f);
        if (eg < E) v = ea4[(size_t)eg * 4 + f4];
        uint4 t = make_uint4(f2tf32(v.x), f2tf32(v.y), f2tf32(v.z), f2tf32(v.w));
        *(uint4*)(Xs + r * XS1 + 128 + f4 * 4) = t;
    }
    __syncthreads();

    const int r0 = rg * 32 + qr;
    const int nc = cg * 32 + qr;      // B fragment col

    float acc[2][4][4];
    #pragma unroll
    for (int mt = 0; mt < 2; ++mt)
        #pragma unroll
        for (int nt = 0; nt < 4; ++nt)
            #pragma unroll
            for (int x = 0; x < 4; ++x) acc[mt][nt][x] = 0.f;

    // ================= GEMM1: X[128,144] @ W1 -> 64 =================
    #pragma unroll 3
    for (int ks = 0; ks < 18; ++ks) {
        int k0 = ks * 8;
        uint32_t a[2][4];
        #pragma unroll
        for (int mt = 0; mt < 2; ++mt) {
            const uint32_t* xr = Xs + (r0 + mt * 16) * XS1 + k0 + qc;
            a[mt][0] = xr[0];
            a[mt][1] = xr[8 * XS1];
            a[mt][2] = xr[4];
            a[mt][3] = xr[8 * XS1 + 4];
        }
        const uint32_t* wb = W1s + (k0 + qc) * WS + nc;
        #pragma unroll
        for (int nt = 0; nt < 4; ++nt) {
            uint32_t b0 = wb[nt * 8];
            uint32_t b1 = wb[4 * WS + nt * 8];
            MMA_TF32(acc[0][nt], a[0], b0, b1);
            MMA_TF32(acc[1][nt], a[1], b0, b1);
        }
    }

    // ---- LN1 + leaky -> H (tf32, stride 68) ----
    {
        float s[4] = {0, 0, 0, 0}, ss[4] = {0, 0, 0, 0};
        #pragma unroll
        for (int mt = 0; mt < 2; ++mt)
            #pragma unroll
            for (int nt = 0; nt < 4; ++nt)
                #pragma unroll
                for (int x = 0; x < 4; ++x) {
                    int h = x >> 1, j = x & 1;
                    int col = cg * 32 + nt * 8 + 2 * qc + j;
                    float v = acc[mt][nt][x] + prm[col];
                    acc[mt][nt][x] = v;
                    s[mt * 2 + h] += v; ss[mt * 2 + h] += v * v;
                }
        #pragma unroll
        for (int o = 1; o <= 2; o <<= 1)
            #pragma unroll
            for (int i = 0; i < 4; ++i) {
                s[i]  += __shfl_xor_sync(0xffffffffu, s[i],  o);
                ss[i] += __shfl_xor_sync(0xffffffffu, ss[i], o);
            }
        if (qc == 0)
            #pragma unroll
            for (int i = 0; i < 4; ++i) {
                int row = rg * 32 + (i >> 1) * 16 + qr + (i & 1) * 8;
                red[row * 2 + cg] = make_float2(s[i], ss[i]);
            }
        __syncthreads();
        float mu[4], rs[4];
        #pragma unroll
        for (int i = 0; i < 4; ++i) {
            int row = rg * 32 + (i >> 1) * 16 + qr + (i & 1) * 8;
            float2 o = red[row * 2 + (cg ^ 1)];
            float S = s[i] + o.x, SS = ss[i] + o.y;
            mu[i] = S * (1.f / 64.f);
            rs[i] = rsqrtf(SS * (1.f / 64.f) - mu[i] * mu[i] + 1e-5f);
        }
        #pragma unroll
        for (int mt = 0; mt < 2; ++mt)
            #pragma unroll
            for (int nt = 0; nt < 4; ++nt)
                #pragma unroll
                for (int h = 0; h < 2; ++h) {
                    int i = mt * 2 + h;
                    int row = rg * 32 + mt * 16 + qr + h * 8;
                    int colb = cg * 32 + nt * 8 + 2 * qc;
                    float y0 = (acc[mt][nt][2 * h]     - mu[i]) * rs[i] * prm[64 + colb]     + prm[128 + colb];
                    float y1 = (acc[mt][nt][2 * h + 1] - mu[i]) * rs[i] * prm[64 + colb + 1] + prm[128 + colb + 1];
                    y0 = (y0 < 0.f) ? 0.1f * y0 : y0;
                    y1 = (y1 < 0.f) ? 0.1f * y1 : y1;
                    *(uint2*)(Xs + row * HS + colb) = make_uint2(f2tf32(y0), f2tf32(y1));
                }
    }
    __syncthreads();

    // ================= GEMM2: H[128,64] @ W2 -> 64 =================
    #pragma unroll
    for (int mt = 0; mt < 2; ++mt)
        #pragma unroll
        for (int nt = 0; nt < 4; ++nt)
            #pragma unroll
            for (int x = 0; x < 4; ++x) acc[mt][nt][x] = 0.f;

    #pragma unroll
    for (int ks = 0; ks < 8; ++ks) {
        int k0 = ks * 8;
        uint32_t a[2][4];
        #pragma unroll
        for (int mt = 0; mt < 2; ++mt) {
            const uint32_t* xr = Xs + (r0 + mt * 16) * HS + k0 + qc;
            a[mt][0] = xr[0];
            a[mt][1] = xr[8 * HS];
            a[mt][2] = xr[4];
            a[mt][3] = xr[8 * HS + 4];
        }
        const uint32_t* wb = W2s + (k0 + qc) * WS + nc;
        #pragma unroll
        for (int nt = 0; nt < 4; ++nt) {
            uint32_t b0 = wb[nt * 8];
            uint32_t b1 = wb[4 * WS + nt * 8];
            MMA_TF32(acc[0][nt], a[0], b0, b1);
            MMA_TF32(acc[1][nt], a[1], b0, b1);
        }
    }

    // ---- LN2 + leaky + W3 dot + store ----
    {
        float s[4] = {0, 0, 0, 0}, ss[4] = {0, 0, 0, 0};
        #pragma unroll
        for (int mt = 0; mt < 2; ++mt)
            #pragma unroll
            for (int nt = 0; nt < 4; ++nt)
                #pragma unroll
                for (int x = 0; x < 4; ++x) {
                    int h = x >> 1, j = x & 1;
                    int col = cg * 32 + nt * 8 + 2 * qc + j;
                    float v = acc[mt][nt][x] + prm[192 + col];
                    acc[mt][nt][x] = v;
                    s[mt * 2 + h] += v; ss[mt * 2 + h] += v * v;
                }
        #pragma unroll
        for (int o = 1; o <= 2; o <<= 1)
            #pragma unroll
            for (int i = 0; i < 4; ++i) {
                s[i]  += __shfl_xor_sync(0xffffffffu, s[i],  o);
                ss[i] += __shfl_xor_sync(0xffffffffu, ss[i], o);
            }
        if (qc == 0)
            #pragma unroll
            for (int i = 0; i < 4; ++i) {
                int row = rg * 32 + (i >> 1) * 16 + qr + (i & 1) * 8;
                red[row * 2 + cg] = make_float2(s[i], ss[i]);
            }
        __syncthreads();
        float mu[4], rs[4];
        #pragma unroll
        for (int i = 0; i < 4; ++i) {
            int row = rg * 32 + (i >> 1) * 16 + qr + (i & 1) * 8;
            float2 o = red[row * 2 + (cg ^ 1)];
            float S = s[i] + o.x, SS = ss[i] + o.y;
            mu[i] = S * (1.f / 64.f);
            rs[i] = rsqrtf(SS * (1.f / 64.f) - mu[i] * mu[i] + 1e-5f);
        }
        float p[4] = {0, 0, 0, 0};
        #pragma unroll
        for (int mt = 0; mt < 2; ++mt)
            #pragma unroll
            for (int nt = 0; nt < 4; ++nt)
                #pragma unroll
                for (int x = 0; x < 4; ++x) {
                    int h = x >> 1, j = x & 1;
                    int i = mt * 2 + h;
                    int col = cg * 32 + nt * 8 + 2 * qc + j;
                    float y = (acc[mt][nt][x] - mu[i]) * rs[i] * prm[256 + col] + prm[320 + col];
                    y = (y < 0.f) ? 0.1f * y : y;
                    p[i] += y * prm[384 + col];
                }
        #pragma unroll
        for (int o = 1; o <= 2; o <<= 1)
            #pragma unroll
            for (int i = 0; i < 4; ++i)
                p[i] += __shfl_xor_sync(0xffffffffu, p[i], o);
        if (qc == 0)
            #pragma unroll
            for (int i = 0; i < 4; ++i) {
                int row = rg * 32 + (i >> 1) * 16 + qr + (i & 1) * 8;
                dot[row * 2 + cg] = p[i];
            }
        __syncthreads();
        if (cg == 0 && qc == 0) {
            #pragma unroll
            for (int i = 0; i < 4; ++i) {
                int row = rg * 32 + (i >> 1) * 16 + qr + (i & 1) * 8;
                float r = dot[row * 2] + dot[row * 2 + 1] + prm[448];
                int eg = eBase + row;
                if (eg < E) out[eg] = r;
            }
        }
    }
}

extern "C" void kernel_launch(void* const* d_in, const int* in_sizes, int n_in,
                              void* d_out, int out_size)
{
    const float* nodef = (const float*)d_in[0];
    const int*   eidx  = (const int*)d_in[1];   // int32 [2, E]
    const float* eattr = (const float*)d_in[2];
    const float* W1  = (const float*)d_in[3];
    const float* B1  = (const float*)d_in[4];
    const float* G1  = (const float*)d_in[5];
    const float* BE1 = (const float*)d_in[6];
    const float* W2  = (const float*)d_in[7];
    const float* B2  = (const float*)d_in[8];
    const float* G2  = (const float*)d_in[9];
    const float* BE2 = (const float*)d_in[10];
    const float* W3  = (const float*)d_in[11];
    const float* B3  = (const float*)d_in[12];
    float* out = (float*)d_out;

    int E      = out_size;
    int nNodes = in_sizes[0] / 64;
    int grid   = (E + 127) / 128;

    cudaFuncSetAttribute(edgenet_mma,
                         cudaFuncAttributeMaxDynamicSharedMemorySize, SMEM_BYTES);
    edgenet_mma<<<grid, 256, SMEM_BYTES>>>(
        nodef, eidx, eattr, W1, B1, G1, BE1, W2, B2, G2, BE2, W3, B3,
        out, E, nNodes);
}

// round 8
// speedup vs baseline: 3.6672x; 1.9939x over previous
#include <cuda_runtime.h>
#include <cstdint>

// EdgeNetwork R7 — mma.sync tf32, occupancy x2 + weight-staging amortization.
// Phased GEMM1 (src/dst/attr k-chunks) shrinks X buffer to 128x68 words ->
// 99.6KB smem/CTA -> 2 CTAs/SM. Each CTA loops 8 edge tiles (weights staged once).

#define XS  68    // X/H row stride (words); 68 % 32 == 4 -> conflict-free frags
#define WS  72    // W row stride; 72 % 32 == 8 -> conflict-free B frags
#define TPB 8     // edge tiles (128 edges) per CTA

#define X_OFF   0
#define W1_OFF  (128 * XS)                   // 8704
#define W2_OFF  (W1_OFF + 144 * WS)          // 19072
#define PRM_OFF (W2_OFF + 64 * WS)           // 23680
#define RED_OFF (PRM_OFF + 452)              // 24132
#define DOT_OFF (RED_OFF + 512)              // 24644
#define SMEM_WORDS (DOT_OFF + 256)           // 24900
#define SMEM_BYTES (SMEM_WORDS * 4)          // 99600

__device__ __forceinline__ uint32_t f2tf32(float f) {
    uint32_t r;
    asm("cvt.rna.tf32.f32 %0, %1;" : "=r"(r) : "f"(f));
    return r;
}

#define MMA_TF32(d, a, b0, b1) \
    asm volatile("mma.sync.aligned.m16n8k8.row.col.f32.tf32.tf32.f32 " \
        "{%0,%1,%2,%3}, {%4,%5,%6,%7}, {%8,%9}, {%0,%1,%2,%3};" \
        : "+f"((d)[0]), "+f"((d)[1]), "+f"((d)[2]), "+f"((d)[3]) \
        : "r"((a)[0]), "r"((a)[1]), "r"((a)[2]), "r"((a)[3]), "r"(b0), "r"(b1))

__global__ __launch_bounds__(256, 2)
void edgenet_mma(const float* __restrict__ nodef,
                 const int* __restrict__ eidx,
                 const float* __restrict__ eattr,
                 const float* __restrict__ W1, const float* __restrict__ pB1,
                 const float* __restrict__ G1, const float* __restrict__ BE1,
                 const float* __restrict__ W2, const float* __restrict__ pB2,
                 const float* __restrict__ G2, const float* __restrict__ BE2,
                 const float* __restrict__ W3, const float* __restrict__ pB3,
                 float* __restrict__ out, int E, int nNodes)
{
    extern __shared__ uint32_t smem[];
    uint32_t* Xs  = smem + X_OFF;
    uint32_t* W1s = smem + W1_OFF;
    uint32_t* W2s = smem + W2_OFF;
    float*    prm = (float*)(smem + PRM_OFF);
    float2*   red = (float2*)(smem + RED_OFF);
    float*    dot = (float*)(smem + DOT_OFF);

    const int tid  = threadIdx.x;
    const int lane = tid & 31;
    const int wid  = tid >> 5;
    const int rg   = wid >> 1;
    const int cg   = wid & 1;
    const int qr   = lane >> 2;
    const int qc   = lane & 3;

    // ---- stage weights (k-major) + params, once per CTA ----
    for (int i = tid; i < 144 * 64; i += 256) {
        int k = i >> 6, n = i & 63;
        W1s[k * WS + n] = f2tf32(W1[i]);
    }
    for (int i = tid; i < 64 * 64; i += 256) {
        int k = i >> 6, n = i & 63;
        W2s[k * WS + n] = f2tf32(W2[i]);
    }
    if (tid < 64) {
        prm[tid]       = pB1[tid];
        prm[64 + tid]  = G1[tid];
        prm[128 + tid] = BE1[tid];
        prm[192 + tid] = pB2[tid];
        prm[256 + tid] = G2[tid];
        prm[320 + tid] = BE2[tid];
        prm[384 + tid] = W3[tid];
    }
    if (tid == 0) prm[448] = pB3[0];

    const float4* nf4 = (const float4*)nodef;
    const float4* ea4 = (const float4*)eattr;
    const int r0 = rg * 32 + qr;
    const int nc = cg * 32 + qr;

    for (int it = 0; it < TPB; ++it) {
        const int eBase = (blockIdx.x * TPB + it) * 128;
        if (eBase >= E) break;

        float acc[2][4][4];
        #pragma unroll
        for (int mt = 0; mt < 2; ++mt)
            #pragma unroll
            for (int nt = 0; nt < 4; ++nt)
                #pragma unroll
                for (int x = 0; x < 4; ++x) acc[mt][nt][x] = 0.f;

        // ===== GEMM1 phases: src (W rows 0-63), dst (64-127), attr (128-143)
        #pragma unroll
        for (int ph = 0; ph < 2; ++ph) {
            __syncthreads();   // X buffer free (prev phase/tile reads done)
            #pragma unroll
            for (int i = 0; i < 8; ++i) {
                int r  = wid * 16 + i * 2 + (lane >> 4);
                int f4 = lane & 15;
                int eg = eBase + r;
                int node = 0;
                if (eg < E) node = ph ? eidx[(size_t)E + eg] : eidx[eg];
                if (node < 0) node = 0;
                if (node >= nNodes) node = nNodes - 1;
                float4 v = nf4[(size_t)node * 16 + f4];
                uint4 t = make_uint4(f2tf32(v.x), f2tf32(v.y), f2tf32(v.z), f2tf32(v.w));
                *(uint4*)(Xs + r * XS + f4 * 4) = t;
            }
            __syncthreads();

            const int wof = ph * 64;
            #pragma unroll
            for (int ks = 0; ks < 8; ++ks) {
                int k0 = ks * 8;
                uint32_t a[2][4];
                #pragma unroll
                for (int mt = 0; mt < 2; ++mt) {
                    const uint32_t* xr = Xs + (r0 + mt * 16) * XS + k0 + qc;
                    a[mt][0] = xr[0];
                    a[mt][1] = xr[8 * XS];
                    a[mt][2] = xr[4];
                    a[mt][3] = xr[8 * XS + 4];
                }
                const uint32_t* wb = W1s + (wof + k0 + qc) * WS + nc;
                #pragma unroll
                for (int nt = 0; nt < 4; ++nt) {
                    uint32_t b0 = wb[nt * 8];
                    uint32_t b1 = wb[4 * WS + nt * 8];
                    MMA_TF32(acc[0][nt], a[0], b0, b1);
                    MMA_TF32(acc[1][nt], a[1], b0, b1);
                }
            }
        }
        {   // attr phase: 16 k-cols, W rows 128-143
            __syncthreads();
            #pragma unroll
            for (int t2 = 0; t2 < 2; ++t2) {
                int j = tid + t2 * 256;
                int r = j >> 2, f4 = j & 3;
                int eg = eBase + r;
                float4 v = make_float4(0.f, 0.f, 0.f, 0.f);
                if (eg < E) v = ea4[(size_t)eg * 4 + f4];
                uint4 t = make_uint4(f2tf32(v.x), f2tf32(v.y), f2tf32(v.z), f2tf32(v.w));
                *(uint4*)(Xs + r * XS + f4 * 4) = t;
            }
            __syncthreads();
            #pragma unroll
            for (int ks = 0; ks < 2; ++ks) {
                int k0 = ks * 8;
                uint32_t a[2][4];
                #pragma unroll
                for (int mt = 0; mt < 2; ++mt) {
                    const uint32_t* xr = Xs + (r0 + mt * 16) * XS + k0 + qc;
                    a[mt][0] = xr[0];
                    a[mt][1] = xr[8 * XS];
                    a[mt][2] = xr[4];
                    a[mt][3] = xr[8 * XS + 4];
                }
                const uint32_t* wb = W1s + (128 + k0 + qc) * WS + nc;
                #pragma unroll
                for (int nt = 0; nt < 4; ++nt) {
                    uint32_t b0 = wb[nt * 8];
                    uint32_t b1 = wb[4 * WS + nt * 8];
                    MMA_TF32(acc[0][nt], a[0], b0, b1);
                    MMA_TF32(acc[1][nt], a[1], b0, b1);
                }
            }
        }

        // ---- LN1 + leaky -> H (into X buffer, stride XS) ----
        {
            float s[4] = {0, 0, 0, 0}, ss[4] = {0, 0, 0, 0};
            #pragma unroll
            for (int mt = 0; mt < 2; ++mt)
                #pragma unroll
                for (int nt = 0; nt < 4; ++nt)
                    #pragma unroll
                    for (int x = 0; x < 4; ++x) {
                        int h = x >> 1, j = x & 1;
                        int col = cg * 32 + nt * 8 + 2 * qc + j;
                        float v = acc[mt][nt][x] + prm[col];
                        acc[mt][nt][x] = v;
                        s[mt * 2 + h] += v; ss[mt * 2 + h] += v * v;
                    }
            #pragma unroll
            for (int o = 1; o <= 2; o <<= 1)
                #pragma unroll
                for (int i = 0; i < 4; ++i) {
                    s[i]  += __shfl_xor_sync(0xffffffffu, s[i],  o);
                    ss[i] += __shfl_xor_sync(0xffffffffu, ss[i], o);
                }
            if (qc == 0)
                #pragma unroll
                for (int i = 0; i < 4; ++i) {
                    int row = rg * 32 + (i >> 1) * 16 + qr + (i & 1) * 8;
                    red[row * 2 + cg] = make_float2(s[i], ss[i]);
                }
            __syncthreads();
            float mu[4], rs[4];
            #pragma unroll
            for (int i = 0; i < 4; ++i) {
                int row = rg * 32 + (i >> 1) * 16 + qr + (i & 1) * 8;
                float2 o = red[row * 2 + (cg ^ 1)];
                float S = s[i] + o.x, SS = ss[i] + o.y;
                mu[i] = S * (1.f / 64.f);
                rs[i] = rsqrtf(SS * (1.f / 64.f) - mu[i] * mu[i] + 1e-5f);
            }
            #pragma unroll
            for (int mt = 0; mt < 2; ++mt)
                #pragma unroll
                for (int nt = 0; nt < 4; ++nt)
                    #pragma unroll
                    for (int h = 0; h < 2; ++h) {
                        int i = mt * 2 + h;
                        int row = rg * 32 + mt * 16 + qr + h * 8;
                        int colb = cg * 32 + nt * 8 + 2 * qc;
                        float y0 = (acc[mt][nt][2*h]   - mu[i]) * rs[i] * prm[64 + colb]   + prm[128 + colb];
                        float y1 = (acc[mt][nt][2*h+1] - mu[i]) * rs[i] * prm[64 + colb+1] + prm[128 + colb+1];
                        y0 = (y0 < 0.f) ? 0.1f * y0 : y0;
                        y1 = (y1 < 0.f) ? 0.1f * y1 : y1;
                        *(uint2*)(Xs + row * XS + colb) = make_uint2(f2tf32(y0), f2tf32(y1));
                    }
        }
        __syncthreads();

        // ===== GEMM2: H[128,64] @ W2 =====
        #pragma unroll
        for (int mt = 0; mt < 2; ++mt)
            #pragma unroll
            for (int nt = 0; nt < 4; ++nt)
                #pragma unroll
                for (int x = 0; x < 4; ++x) acc[mt][nt][x] = 0.f;

        #pragma unroll
        for (int ks = 0; ks < 8; ++ks) {
            int k0 = ks * 8;
            uint32_t a[2][4];
            #pragma unroll
            for (int mt = 0; mt < 2; ++mt) {
                const uint32_t* xr = Xs + (r0 + mt * 16) * XS + k0 + qc;
                a[mt][0] = xr[0];
                a[mt][1] = xr[8 * XS];
                a[mt][2] = xr[4];
                a[mt][3] = xr[8 * XS + 4];
            }
            const uint32_t* wb = W2s + (k0 + qc) * WS + nc;
            #pragma unroll
            for (int nt = 0; nt < 4; ++nt) {
                uint32_t b0 = wb[nt * 8];
                uint32_t b1 = wb[4 * WS + nt * 8];
                MMA_TF32(acc[0][nt], a[0], b0, b1);
                MMA_TF32(acc[1][nt], a[1], b0, b1);
            }
        }

        // ---- LN2 + leaky + W3 dot + store ----
        {
            float s[4] = {0, 0, 0, 0}, ss[4] = {0, 0, 0, 0};
            #pragma unroll
            for (int mt = 0; mt < 2; ++mt)
                #pragma unroll
                for (int nt = 0; nt < 4; ++nt)
                    #pragma unroll
                    for (int x = 0; x < 4; ++x) {
                        int h = x >> 1, j = x & 1;
                        int col = cg * 32 + nt * 8 + 2 * qc + j;
                        float v = acc[mt][nt][x] + prm[192 + col];
                        acc[mt][nt][x] = v;
                        s[mt * 2 + h] += v; ss[mt * 2 + h] += v * v;
                    }
            #pragma unroll
            for (int o = 1; o <= 2; o <<= 1)
                #pragma unroll
                for (int i = 0; i < 4; ++i) {
                    s[i]  += __shfl_xor_sync(0xffffffffu, s[i],  o);
                    ss[i] += __shfl_xor_sync(0xffffffffu, ss[i], o);
                }
            if (qc == 0)
                #pragma unroll
                for (int i = 0; i < 4; ++i) {
                    int row = rg * 32 + (i >> 1) * 16 + qr + (i & 1) * 8;
                    red[row * 2 + cg] = make_float2(s[i], ss[i]);
                }
            __syncthreads();
            float mu[4], rs[4];
            #pragma unroll
            for (int i = 0; i < 4; ++i) {
                int row = rg * 32 + (i >> 1) * 16 + qr + (i & 1) * 8;
                float2 o = red[row * 2 + (cg ^ 1)];
                float S = s[i] + o.x, SS = ss[i] + o.y;
                mu[i] = S * (1.f / 64.f);
                rs[i] = rsqrtf(SS * (1.f / 64.f) - mu[i] * mu[i] + 1e-5f);
            }
            float p[4] = {0, 0, 0, 0};
            #pragma unroll
            for (int mt = 0; mt < 2; ++mt)
                #pragma unroll
                for (int nt = 0; nt < 4; ++nt)
                    #pragma unroll
                    for (int x = 0; x < 4; ++x) {
                        int h = x >> 1, j = x & 1;
                        int i = mt * 2 + h;
                        int col = cg * 32 + nt * 8 + 2 * qc + j;
                        float y = (acc[mt][nt][x] - mu[i]) * rs[i] * prm[256 + col] + prm[320 + col];
                        y = (y < 0.f) ? 0.1f * y : y;
                        p[i] += y * prm[384 + col];
                    }
            #pragma unroll
            for (int o = 1; o <= 2; o <<= 1)
                #pragma unroll
                for (int i = 0; i < 4; ++i)
                    p[i] += __shfl_xor_sync(0xffffffffu, p[i], o);
            if (qc == 0)
                #pragma unroll
                for (int i = 0; i < 4; ++i) {
                    int row = rg * 32 + (i >> 1) * 16 + qr + (i & 1) * 8;
                    dot[row * 2 + cg] = p[i];
                }
            __syncthreads();
            if (cg == 0 && qc == 0) {
                #pragma unroll
                for (int i = 0; i < 4; ++i) {
                    int row = rg * 32 + (i >> 1) * 16 + qr + (i & 1) * 8;
                    float r = dot[row * 2] + dot[row * 2 + 1] + prm[448];
                    int eg = eBase + row;
                    if (eg < E) out[eg] = r;
                }
            }
        }
    }
}

extern "C" void kernel_launch(void* const* d_in, const int* in_sizes, int n_in,
                              void* d_out, int out_size)
{
    const float* nodef = (const float*)d_in[0];
    const int*   eidx  = (const int*)d_in[1];   // int32 [2, E]
    const float* eattr = (const float*)d_in[2];
    const float* W1  = (const float*)d_in[3];
    const float* B1  = (const float*)d_in[4];
    const float* G1  = (const float*)d_in[5];
    const float* BE1 = (const float*)d_in[6];
    const float* W2  = (const float*)d_in[7];
    const float* B2  = (const float*)d_in[8];
    const float* G2  = (const float*)d_in[9];
    const float* BE2 = (const float*)d_in[10];
    const float* W3  = (const float*)d_in[11];
    const float* B3  = (const float*)d_in[12];
    float* out = (float*)d_out;

    int E       = out_size;
    int nNodes  = in_sizes[0] / 64;
    int nTiles  = (E + 127) / 128;
    int grid    = (nTiles + TPB - 1) / TPB;

    cudaFuncSetAttribute(edgenet_mma,
                         cudaFuncAttributeMaxDynamicSharedMemorySize, SMEM_BYTES);
    edgenet_mma<<<grid, 256, SMEM_BYTES>>>(
        nodef, eidx, eattr, W1, B1, G1, BE1, W2, B2, G2, BE2, W3, B3,
        out, E, nNodes);
}

// round 9
// speedup vs baseline: 5.3123x; 1.4486x over previous
#include <cuda_runtime.h>
#include <cuda_fp16.h>
#include <cstdint>

// EdgeNetwork R9 — fp16 m16n8k16 mma.sync (same 11-bit mantissa as tf32,
// half the LDS traffic and half the MMA instructions). Full X tile resident
// (no GEMM1 phasing). CTA = 256 thr, 128-edge tiles x TPB, 2 CTAs/SM.

#define XSW 76    // X row stride (words of half2); 76 % 8 == 4 -> conflict-free
#define HSW 36    // H row stride (words); 36 % 8 == 4
#define WPS 72    // W pair-row stride (words); 72 % 32 == 8
#define TPB 8

#define X_OFF   0
#define W1_OFF  (128 * XSW)                  // 9728
#define W2_OFF  (W1_OFF + 72 * WPS)          // 14912
#define PRM_OFF (W2_OFF + 32 * WPS)          // 17216
#define RED_OFF (PRM_OFF + 452)              // 17668
#define DOT_OFF (RED_OFF + 512)              // 18180
#define SMEM_WORDS (DOT_OFF + 256)           // 18436
#define SMEM_BYTES (SMEM_WORDS * 4)          // 73744

__device__ __forceinline__ uint32_t h2pack(float lo, float hi) {
    __half2 h = __floats2half2_rn(lo, hi);
    return *(uint32_t*)&h;
}

#define MMA_F16(d, a, b0, b1) \
    asm volatile("mma.sync.aligned.m16n8k16.row.col.f32.f16.f16.f32 " \
        "{%0,%1,%2,%3}, {%4,%5,%6,%7}, {%8,%9}, {%0,%1,%2,%3};" \
        : "+f"((d)[0]), "+f"((d)[1]), "+f"((d)[2]), "+f"((d)[3]) \
        : "r"((a)[0]), "r"((a)[1]), "r"((a)[2]), "r"((a)[3]), "r"(b0), "r"(b1))

__global__ __launch_bounds__(256, 2)
void edgenet_mma(const float* __restrict__ nodef,
                 const int* __restrict__ eidx,
                 const float* __restrict__ eattr,
                 const float* __restrict__ W1, const float* __restrict__ pB1,
                 const float* __restrict__ G1, const float* __restrict__ BE1,
                 const float* __restrict__ W2, const float* __restrict__ pB2,
                 const float* __restrict__ G2, const float* __restrict__ BE2,
                 const float* __restrict__ W3, const float* __restrict__ pB3,
                 float* __restrict__ out, int E, int nNodes)
{
    extern __shared__ uint32_t smem[];
    uint32_t* Xs  = smem + X_OFF;      // fp16 X tile / H tile
    uint32_t* W1p = smem + W1_OFF;     // half2(W1[2p][n], W1[2p+1][n])
    uint32_t* W2p = smem + W2_OFF;
    float*    prm = (float*)(smem + PRM_OFF);
    float2*   red = (float2*)(smem + RED_OFF);
    float*    dot = (float*)(smem + DOT_OFF);

    const int tid  = threadIdx.x;
    const int lane = tid & 31;
    const int wid  = tid >> 5;
    const int rg   = wid >> 1;
    const int cg   = wid & 1;
    const int qr   = lane >> 2;
    const int qc   = lane & 3;

    // ---- stage weights as k-pair half2, once per CTA ----
    for (int i = tid; i < 72 * 64; i += 256) {
        int p = i >> 6, n = i & 63;
        W1p[p * WPS + n] = h2pack(W1[(2 * p) * 64 + n], W1[(2 * p + 1) * 64 + n]);
    }
    for (int i = tid; i < 32 * 64; i += 256) {
        int p = i >> 6, n = i & 63;
        W2p[p * WPS + n] = h2pack(W2[(2 * p) * 64 + n], W2[(2 * p + 1) * 64 + n]);
    }
    if (tid < 64) {
        prm[tid]       = pB1[tid];
        prm[64 + tid]  = G1[tid];
        prm[128 + tid] = BE1[tid];
        prm[192 + tid] = pB2[tid];
        prm[256 + tid] = G2[tid];
        prm[320 + tid] = BE2[tid];
        prm[384 + tid] = W3[tid];
    }
    if (tid == 0) prm[448] = pB3[0];

    const float4* nf4 = (const float4*)nodef;
    const float4* ea4 = (const float4*)eattr;
    const int r0 = rg * 32 + qr;
    const int nc = cg * 32 + qr;

    for (int it = 0; it < TPB; ++it) {
        const int eBase = (blockIdx.x * TPB + it) * 128;
        if (eBase >= E) break;

        // ---- gather full X tile (fp16): src | dst | attr ----
        #pragma unroll
        for (int half = 0; half < 2; ++half) {
            #pragma unroll
            for (int i = 0; i < 8; ++i) {
                int r  = wid * 16 + i * 2 + (lane >> 4);
                int f4 = lane & 15;
                int eg = eBase + r;
                int node = 0;
                if (eg < E) node = half ? eidx[(size_t)E + eg] : eidx[eg];
                if (node < 0) node = 0;
                if (node >= nNodes) node = nNodes - 1;
                float4 v = nf4[(size_t)node * 16 + f4];
                *(uint2*)(Xs + r * XSW + half * 32 + f4 * 2) =
                    make_uint2(h2pack(v.x, v.y), h2pack(v.z, v.w));
            }
        }
        #pragma unroll
        for (int t2 = 0; t2 < 2; ++t2) {
            int j = tid + t2 * 256;
            int r = j >> 2, f4 = j & 3;
            int eg = eBase + r;
            float4 v = make_float4(0.f, 0.f, 0.f, 0.f);
            if (eg < E) v = ea4[(size_t)eg * 4 + f4];
            *(uint2*)(Xs + r * XSW + 64 + f4 * 2) =
                make_uint2(h2pack(v.x, v.y), h2pack(v.z, v.w));
        }
        __syncthreads();

        float acc[2][4][4];
        #pragma unroll
        for (int mt = 0; mt < 2; ++mt)
            #pragma unroll
            for (int nt = 0; nt < 4; ++nt)
                #pragma unroll
                for (int x = 0; x < 4; ++x) acc[mt][nt][x] = 0.f;

        // ===== GEMM1: X[128,144] @ W1  (9 k16 steps) =====
        #pragma unroll 3
        for (int ks = 0; ks < 9; ++ks) {
            int kw = ks * 8;   // pair index base
            uint32_t a[2][4];
            #pragma unroll
            for (int mt = 0; mt < 2; ++mt) {
                const uint32_t* xr = Xs + (r0 + mt * 16) * XSW + kw + qc;
                a[mt][0] = xr[0];
                a[mt][1] = xr[8 * XSW];
                a[mt][2] = xr[4];
                a[mt][3] = xr[8 * XSW + 4];
            }
            const uint32_t* wb = W1p + (kw + qc) * WPS + nc;
            #pragma unroll
            for (int nt = 0; nt < 4; ++nt) {
                uint32_t b0 = wb[nt * 8];
                uint32_t b1 = wb[4 * WPS + nt * 8];
                MMA_F16(acc[0][nt], a[0], b0, b1);
                MMA_F16(acc[1][nt], a[1], b0, b1);
            }
        }

        // ---- LN1 + leaky -> H (fp16, stride HSW) ----
        {
            float s[4] = {0, 0, 0, 0}, ss[4] = {0, 0, 0, 0};
            #pragma unroll
            for (int mt = 0; mt < 2; ++mt)
                #pragma unroll
                for (int nt = 0; nt < 4; ++nt)
                    #pragma unroll
                    for (int x = 0; x < 4; ++x) {
                        int h = x >> 1, j = x & 1;
                        int col = cg * 32 + nt * 8 + 2 * qc + j;
                        float v = acc[mt][nt][x] + prm[col];
                        acc[mt][nt][x] = v;
                        s[mt * 2 + h] += v; ss[mt * 2 + h] += v * v;
                    }
            #pragma unroll
            for (int o = 1; o <= 2; o <<= 1)
                #pragma unroll
                for (int i = 0; i < 4; ++i) {
                    s[i]  += __shfl_xor_sync(0xffffffffu, s[i],  o);
                    ss[i] += __shfl_xor_sync(0xffffffffu, ss[i], o);
                }
            if (qc == 0)
                #pragma unroll
                for (int i = 0; i < 4; ++i) {
                    int row = rg * 32 + (i >> 1) * 16 + qr + (i & 1) * 8;
                    red[row * 2 + cg] = make_float2(s[i], ss[i]);
                }
            __syncthreads();
            float mu[4], rs[4];
            #pragma unroll
            for (int i = 0; i < 4; ++i) {
                int row = rg * 32 + (i >> 1) * 16 + qr + (i & 1) * 8;
                float2 o = red[row * 2 + (cg ^ 1)];
                float S = s[i] + o.x, SS = ss[i] + o.y;
                mu[i] = S * (1.f / 64.f);
                rs[i] = rsqrtf(SS * (1.f / 64.f) - mu[i] * mu[i] + 1e-5f);
            }
            #pragma unroll
            for (int mt = 0; mt < 2; ++mt)
                #pragma unroll
                for (int nt = 0; nt < 4; ++nt)
                    #pragma unroll
                    for (int h = 0; h < 2; ++h) {
                        int i = mt * 2 + h;
                        int row = rg * 32 + mt * 16 + qr + h * 8;
                        int colb = cg * 32 + nt * 8 + 2 * qc;
                        float y0 = (acc[mt][nt][2*h]   - mu[i]) * rs[i] * prm[64 + colb]   + prm[128 + colb];
                        float y1 = (acc[mt][nt][2*h+1] - mu[i]) * rs[i] * prm[64 + colb+1] + prm[128 + colb+1];
                        y0 = (y0 < 0.f) ? 0.1f * y0 : y0;
                        y1 = (y1 < 0.f) ? 0.1f * y1 : y1;
                        Xs[row * HSW + (colb >> 1)] = h2pack(y0, y1);
                    }
        }
        __syncthreads();

        // ===== GEMM2: H[128,64] @ W2  (4 k16 steps) =====
        #pragma unroll
        for (int mt = 0; mt < 2; ++mt)
            #pragma unroll
            for (int nt = 0; nt < 4; ++nt)
                #pragma unroll
                for (int x = 0; x < 4; ++x) acc[mt][nt][x] = 0.f;

        #pragma unroll
        for (int ks = 0; ks < 4; ++ks) {
            int kw = ks * 8;
            uint32_t a[2][4];
            #pragma unroll
            for (int mt = 0; mt < 2; ++mt) {
                const uint32_t* xr = Xs + (r0 + mt * 16) * HSW + kw + qc;
                a[mt][0] = xr[0];
                a[mt][1] = xr[8 * HSW];
                a[mt][2] = xr[4];
                a[mt][3] = xr[8 * HSW + 4];
            }
            const uint32_t* wb = W2p + (kw + qc) * WPS + nc;
            #pragma unroll
            for (int nt = 0; nt < 4; ++nt) {
                uint32_t b0 = wb[nt * 8];
                uint32_t b1 = wb[4 * WPS + nt * 8];
                MMA_F16(acc[0][nt], a[0], b0, b1);
                MMA_F16(acc[1][nt], a[1], b0, b1);
            }
        }

        // ---- LN2 + leaky + W3 dot + store ----
        {
            float s[4] = {0, 0, 0, 0}, ss[4] = {0, 0, 0, 0};
            #pragma unroll
            for (int mt = 0; mt < 2; ++mt)
                #pragma unroll
                for (int nt = 0; nt < 4; ++nt)
                    #pragma unroll
                    for (int x = 0; x < 4; ++x) {
                        int h = x >> 1, j = x & 1;
                        int col = cg * 32 + nt * 8 + 2 * qc + j;
                        float v = acc[mt][nt][x] + prm[192 + col];
                        acc[mt][nt][x] = v;
                        s[mt * 2 + h] += v; ss[mt * 2 + h] += v * v;
                    }
            #pragma unroll
            for (int o = 1; o <= 2; o <<= 1)
                #pragma unroll
                for (int i = 0; i < 4; ++i) {
                    s[i]  += __shfl_xor_sync(0xffffffffu, s[i],  o);
                    ss[i] += __shfl_xor_sync(0xffffffffu, ss[i], o);
                }
            if (qc == 0)
                #pragma unroll
                for (int i = 0; i < 4; ++i) {
                    int row = rg * 32 + (i >> 1) * 16 + qr + (i & 1) * 8;
                    red[row * 2 + cg] = make_float2(s[i], ss[i]);
                }
            __syncthreads();
            float mu[4], rs[4];
            #pragma unroll
            for (int i = 0; i < 4; ++i) {
                int row = rg * 32 + (i >> 1) * 16 + qr + (i & 1) * 8;
                float2 o = red[row * 2 + (cg ^ 1)];
                float S = s[i] + o.x, SS = ss[i] + o.y;
                mu[i] = S * (1.f / 64.f);
                rs[i] = rsqrtf(SS * (1.f / 64.f) - mu[i] * mu[i] + 1e-5f);
            }
            float p[4] = {0, 0, 0, 0};
            #pragma unroll
            for (int mt = 0; mt < 2; ++mt)
                #pragma unroll
                for (int nt = 0; nt < 4; ++nt)
                    #pragma unroll
                    for (int x = 0; x < 4; ++x) {
                        int h = x >> 1, j = x & 1;
                        int i = mt * 2 + h;
                        int col = cg * 32 + nt * 8 + 2 * qc + j;
                        float y = (acc[mt][nt][x] - mu[i]) * rs[i] * prm[256 + col] + prm[320 + col];
                        y = (y < 0.f) ? 0.1f * y : y;
                        p[i] += y * prm[384 + col];
                    }
            #pragma unroll
            for (int o = 1; o <= 2; o <<= 1)
                #pragma unroll
                for (int i = 0; i < 4; ++i)
                    p[i] += __shfl_xor_sync(0xffffffffu, p[i], o);
            if (qc == 0)
                #pragma unroll
                for (int i = 0; i < 4; ++i) {
                    int row = rg * 32 + (i >> 1) * 16 + qr + (i & 1) * 8;
                    dot[row * 2 + cg] = p[i];
                }
            __syncthreads();
            if (cg == 0 && qc == 0) {
                #pragma unroll
                for (int i = 0; i < 4; ++i) {
                    int row = rg * 32 + (i >> 1) * 16 + qr + (i & 1) * 8;
                    float r = dot[row * 2] + dot[row * 2 + 1] + prm[448];
                    int eg = eBase + row;
                    if (eg < E) out[eg] = r;
                }
            }
        }
        __syncthreads();   // protect X overwrite by next tile's gather
    }
}

extern "C" void kernel_launch(void* const* d_in, const int* in_sizes, int n_in,
                              void* d_out, int out_size)
{
    const float* nodef = (const float*)d_in[0];
    const int*   eidx  = (const int*)d_in[1];   // int32 [2, E]
    const float* eattr = (const float*)d_in[2];
    const float* W1  = (const float*)d_in[3];
    const float* B1  = (const float*)d_in[4];
    const float* G1  = (const float*)d_in[5];
    const float* BE1 = (const float*)d_in[6];
    const float* W2  = (const float*)d_in[7];
    const float* B2  = (const float*)d_in[8];
    const float* G2  = (const float*)d_in[9];
    const float* BE2 = (const float*)d_in[10];
    const float* W3  = (const float*)d_in[11];
    const float* B3  = (const float*)d_in[12];
    float* out = (float*)d_out;

    int E      = out_size;
    int nNodes = in_sizes[0] / 64;
    int nTiles = (E + 127) / 128;
    int grid   = (nTiles + TPB - 1) / TPB;

    cudaFuncSetAttribute(edgenet_mma,
                         cudaFuncAttributeMaxDynamicSharedMemorySize, SMEM_BYTES);
    edgenet_mma<<<grid, 256, SMEM_BYTES>>>(
        nodef, eidx, eattr, W1, B1, G1, BE1, W2, B2, G2, BE2, W3, B3,
        out, E, nNodes);
}

// round 12
// speedup vs baseline: 6.4448x; 1.2132x over previous
#include <cuda_runtime.h>
#include <cuda_fp16.h>
#include <cstdint>

// EdgeNetwork R10 — fp16 mma.sync, fragment-chained layers.
// 8 warps x (m16 rows x all 64 cols): accumulator fragment IS the next A
// fragment -> H never hits smem; LN reductions are qc-shfl only; gather is
// warp-local -> zero per-tile __syncthreads. 3 CTAs/SM.

#define XSW 76    // X row stride (words); fragment reads conflict-free
#define WPS 72    // W pair-row stride (words); 72 % 32 == 8
#define TPB 8

#define X_OFF   0
#define W1_OFF  (128 * XSW)                  // 9728
#define W2_OFF  (W1_OFF + 72 * WPS)          // 14912
#define PRM_OFF (W2_OFF + 32 * WPS)          // 17216
#define SMEM_WORDS (PRM_OFF + 452)           // 17668
#define SMEM_BYTES (SMEM_WORDS * 4)          // 70672

__device__ __forceinline__ uint32_t h2pack(float lo, float hi) {
    __half2 h = __floats2half2_rn(lo, hi);
    return *(uint32_t*)&h;
}

#define MMA_F16(d, a, b0, b1) \
    asm volatile("mma.sync.aligned.m16n8k16.row.col.f32.f16.f16.f32 " \
        "{%0,%1,%2,%3}, {%4,%5,%6,%7}, {%8,%9}, {%0,%1,%2,%3};" \
        : "+f"((d)[0]), "+f"((d)[1]), "+f"((d)[2]), "+f"((d)[3]) \
        : "r"((a)[0]), "r"((a)[1]), "r"((a)[2]), "r"((a)[3]), "r"(b0), "r"(b1))

__global__ __launch_bounds__(256, 3)
void edgenet_mma(const float* __restrict__ nodef,
                 const int* __restrict__ eidx,
                 const float* __restrict__ eattr,
                 const float* __restrict__ W1, const float* __restrict__ pB1,
                 const float* __restrict__ G1, const float* __restrict__ BE1,
                 const float* __restrict__ W2, const float* __restrict__ pB2,
                 const float* __restrict__ G2, const float* __restrict__ BE2,
                 const float* __restrict__ W3, const float* __restrict__ pB3,
                 float* __restrict__ out, int E, int nNodes)
{
    extern __shared__ uint32_t smem[];
    uint32_t* Xs  = smem + X_OFF;
    uint32_t* W1p = smem + W1_OFF;   // half2(W1[2p][n], W1[2p+1][n])
    uint32_t* W2p = smem + W2_OFF;
    float*    prm = (float*)(smem + PRM_OFF);

    const int tid  = threadIdx.x;
    const int lane = tid & 31;
    const int wid  = tid >> 5;
    const int qr   = lane >> 2;    // 0..7: row within m16 half / B col within n8
    const int qc   = lane & 3;     // 0..3: k-group / col pair

    // ---- stage weights (k-pair half2) + params, once per CTA ----
    for (int i = tid; i < 72 * 64; i += 256) {
        int p = i >> 6, n = i & 63;
        W1p[p * WPS + n] = h2pack(W1[(2 * p) * 64 + n], W1[(2 * p + 1) * 64 + n]);
    }
    for (int i = tid; i < 32 * 64; i += 256) {
        int p = i >> 6, n = i & 63;
        W2p[p * WPS + n] = h2pack(W2[(2 * p) * 64 + n], W2[(2 * p + 1) * 64 + n]);
    }
    if (tid < 64) {
        prm[tid]       = pB1[tid];
        prm[64 + tid]  = G1[tid];
        prm[128 + tid] = BE1[tid];
        prm[192 + tid] = pB2[tid];
        prm[256 + tid] = G2[tid];
        prm[320 + tid] = BE2[tid];
        prm[384 + tid] = W3[tid];
    }
    if (tid == 0) prm[448] = pB3[0];
    __syncthreads();   // the only CTA barrier

    const float4* nf4 = (const float4*)nodef;
    const float4* ea4 = (const float4*)eattr;
    const int rBase = wid * 16;          // warp's 16 rows
    const int r0 = rBase + qr;

    for (int it = 0; it < TPB; ++it) {
        const int eBase = (blockIdx.x * TPB + it) * 128;
        if (eBase >= E) break;

        // ---- warp-local gather of this warp's 16 X rows (fp16) ----
        #pragma unroll
        for (int half = 0; half < 2; ++half) {
            #pragma unroll
            for (int i = 0; i < 8; ++i) {
                int r  = rBase + i * 2 + (lane >> 4);
                int f4 = lane & 15;
                int eg = eBase + r;
                int node = 0;
                if (eg < E) node = half ? eidx[(size_t)E + eg] : eidx[eg];
                if (node < 0) node = 0;
                if (node >= nNodes) node = nNodes - 1;
                float4 v = nf4[(size_t)node * 16 + f4];
                *(uint2*)(Xs + r * XSW + half * 32 + f4 * 2) =
                    make_uint2(h2pack(v.x, v.y), h2pack(v.z, v.w));
            }
        }
        #pragma unroll
        for (int t2 = 0; t2 < 2; ++t2) {
            int idx = t2 * 32 + lane;          // 0..63 over 16 rows x 4 f4
            int r = rBase + (idx >> 2), f4 = idx & 3;
            int eg = eBase + r;
            float4 v = make_float4(0.f, 0.f, 0.f, 0.f);
            if (eg < E) v = ea4[(size_t)eg * 4 + f4];
            *(uint2*)(Xs + r * XSW + 64 + f4 * 2) =
                make_uint2(h2pack(v.x, v.y), h2pack(v.z, v.w));
        }
        __syncwarp();

        // ===== GEMM1: X[16,144] @ W1 -> acc[8 ntiles][4] =====
        float acc[8][4];
        #pragma unroll
        for (int nt = 0; nt < 8; ++nt)
            #pragma unroll
            for (int x = 0; x < 4; ++x) acc[nt][x] = 0.f;

        #pragma unroll 3
        for (int ks = 0; ks < 9; ++ks) {
            int kw = ks * 8;
            uint32_t a[4];
            const uint32_t* xr = Xs + r0 * XSW + kw + qc;
            a[0] = xr[0];
            a[1] = xr[8 * XSW];
            a[2] = xr[4];
            a[3] = xr[8 * XSW + 4];
            const uint32_t* wb = W1p + (kw + qc) * WPS + qr;
            #pragma unroll
            for (int nt = 0; nt < 8; ++nt)
                MMA_F16(acc[nt], a, wb[nt * 8], wb[4 * WPS + nt * 8]);
        }

        // ---- LN1 + leaky, in-register -> GEMM2 A fragments ----
        uint32_t a2[4][4];
        {
            float s0 = 0.f, ss0 = 0.f, s1 = 0.f, ss1 = 0.f;
            #pragma unroll
            for (int nt = 0; nt < 8; ++nt) {
                int colb = nt * 8 + 2 * qc;
                float v0 = acc[nt][0] + prm[colb];
                float v1 = acc[nt][1] + prm[colb + 1];
                float v2 = acc[nt][2] + prm[colb];
                float v3 = acc[nt][3] + prm[colb + 1];
                acc[nt][0] = v0; acc[nt][1] = v1; acc[nt][2] = v2; acc[nt][3] = v3;
                s0 += v0 + v1; ss0 += v0 * v0 + v1 * v1;
                s1 += v2 + v3; ss1 += v2 * v2 + v3 * v3;
            }
            #pragma unroll
            for (int o = 1; o <= 2; o <<= 1) {
                s0  += __shfl_xor_sync(0xffffffffu, s0,  o);
                ss0 += __shfl_xor_sync(0xffffffffu, ss0, o);
                s1  += __shfl_xor_sync(0xffffffffu, s1,  o);
                ss1 += __shfl_xor_sync(0xffffffffu, ss1, o);
            }
            float mu0 = s0 * (1.f / 64.f);
            float rs0 = rsqrtf(ss0 * (1.f / 64.f) - mu0 * mu0 + 1e-5f);
            float mu1 = s1 * (1.f / 64.f);
            float rs1 = rsqrtf(ss1 * (1.f / 64.f) - mu1 * mu1 + 1e-5f);
            #pragma unroll
            for (int nt = 0; nt < 8; ++nt) {
                int colb = nt * 8 + 2 * qc;
                float g0 = prm[64 + colb], g1 = prm[64 + colb + 1];
                float e0 = prm[128 + colb], e1 = prm[128 + colb + 1];
                float y0 = (acc[nt][0] - mu0) * rs0 * g0 + e0;
                float y1 = (acc[nt][1] - mu0) * rs0 * g1 + e1;
                float y2 = (acc[nt][2] - mu1) * rs1 * g0 + e0;
                float y3 = (acc[nt][3] - mu1) * rs1 * g1 + e1;
                y0 = (y0 < 0.f) ? 0.1f * y0 : y0;
                y1 = (y1 < 0.f) ? 0.1f * y1 : y1;
                y2 = (y2 < 0.f) ? 0.1f * y2 : y2;
                y3 = (y3 < 0.f) ? 0.1f * y3 : y3;
                // acc fragment == A fragment: a2[ks][0,1]=ntile 2ks rows qr,qr+8
                a2[nt >> 1][(nt & 1) * 2]     = h2pack(y0, y1);
                a2[nt >> 1][(nt & 1) * 2 + 1] = h2pack(y2, y3);
            }
        }

        // ===== GEMM2: H[16,64] @ W2 (A from registers) =====
        float ac2[8][4];
        #pragma unroll
        for (int nt = 0; nt < 8; ++nt)
            #pragma unroll
            for (int x = 0; x < 4; ++x) ac2[nt][x] = 0.f;

        #pragma unroll
        for (int ks = 0; ks < 4; ++ks) {
            const uint32_t* wb = W2p + (ks * 8 + qc) * WPS + qr;
            #pragma unroll
            for (int nt = 0; nt < 8; ++nt)
                MMA_F16(ac2[nt], a2[ks], wb[nt * 8], wb[4 * WPS + nt * 8]);
        }

        // ---- LN2 + leaky + W3 dot + store (shfl-only) ----
        {
            float s0 = 0.f, ss0 = 0.f, s1 = 0.f, ss1 = 0.f;
            #pragma unroll
            for (int nt = 0; nt < 8; ++nt) {
                int colb = nt * 8 + 2 * qc;
                float v0 = ac2[nt][0] + prm[192 + colb];
                float v1 = ac2[nt][1] + prm[192 + colb + 1];
                float v2 = ac2[nt][2] + prm[192 + colb];
                float v3 = ac2[nt][3] + prm[192 + colb + 1];
                ac2[nt][0] = v0; ac2[nt][1] = v1; ac2[nt][2] = v2; ac2[nt][3] = v3;
                s0 += v0 + v1; ss0 += v0 * v0 + v1 * v1;
                s1 += v2 + v3; ss1 += v2 * v2 + v3 * v3;
            }
            #pragma unroll
            for (int o = 1; o <= 2; o <<= 1) {
                s0  += __shfl_xor_sync(0xffffffffu, s0,  o);
                ss0 += __shfl_xor_sync(0xffffffffu, ss0, o);
                s1  += __shfl_xor_sync(0xffffffffu, s1,  o);
                ss1 += __shfl_xor_sync(0xffffffffu, ss1, o);
            }
            float mu0 = s0 * (1.f / 64.f);
            float rs0 = rsqrtf(ss0 * (1.f / 64.f) - mu0 * mu0 + 1e-5f);
            float mu1 = s1 * (1.f / 64.f);
            float rs1 = rsqrtf(ss1 * (1.f / 64.f) - mu1 * mu1 + 1e-5f);

            float p0 = 0.f, p1 = 0.f;
            #pragma unroll
            for (int nt = 0; nt < 8; ++nt) {
                int colb = nt * 8 + 2 * qc;
                float g0 = prm[256 + colb], g1 = prm[256 + colb + 1];
                float e0 = prm[320 + colb], e1 = prm[320 + colb + 1];
                float w0 = prm[384 + colb], w1 = prm[384 + colb + 1];
                float y0 = (ac2[nt][0] - mu0) * rs0 * g0 + e0;
                float y1 = (ac2[nt][1] - mu0) * rs0 * g1 + e1;
                float y2 = (ac2[nt][2] - mu1) * rs1 * g0 + e0;
                float y3 = (ac2[nt][3] - mu1) * rs1 * g1 + e1;
                y0 = (y0 < 0.f) ? 0.1f * y0 : y0;
                y1 = (y1 < 0.f) ? 0.1f * y1 : y1;
                y2 = (y2 < 0.f) ? 0.1f * y2 : y2;
                y3 = (y3 < 0.f) ? 0.1f * y3 : y3;
                p0 += y0 * w0 + y1 * w1;
                p1 += y2 * w0 + y3 * w1;
            }
            #pragma unroll
            for (int o = 1; o <= 2; o <<= 1) {
                p0 += __shfl_xor_sync(0xffffffffu, p0, o);
                p1 += __shfl_xor_sync(0xffffffffu, p1, o);
            }
            if (qc == 0) {
                float b3 = prm[448];
                int e0i = eBase + r0;
                int e1i = eBase + r0 + 8;
                if (e0i < E) out[e0i] = p0 + b3;
                if (e1i < E) out[e1i] = p1 + b3;
            }
        }
        __syncwarp();   // X rows are warp-private; safe to regather next tile
    }
}

extern "C" void kernel_launch(void* const* d_in, const int* in_sizes, int n_in,
                              void* d_out, int out_size)
{
    const float* nodef = (const float*)d_in[0];
    const int*   eidx  = (const int*)d_in[1];   // int32 [2, E]
    const float* eattr = (const float*)d_in[2];
    const float* W1  = (const float*)d_in[3];
    const float* B1  = (const float*)d_in[4];
    const float* G1  = (const float*)d_in[5];
    const float* BE1 = (const float*)d_in[6];
    const float* W2  = (const float*)d_in[7];
    const float* B2  = (const float*)d_in[8];
    const float* G2  = (const float*)d_in[9];
    const float* BE2 = (const float*)d_in[10];
    const float* W3  = (const float*)d_in[11];
    const float* B3  = (const float*)d_in[12];
    float* out = (float*)d_out;

    int E      = out_size;
    int nNodes = in_sizes[0] / 64;
    int nTiles = (E + 127) / 128;
    int grid   = (nTiles + TPB - 1) / TPB;

    cudaFuncSetAttribute(edgenet_mma,
                         cudaFuncAttributeMaxDynamicSharedMemorySize, SMEM_BYTES);
    edgenet_mma<<<grid, 256, SMEM_BYTES>>>(
        nodef, eidx, eattr, W1, B1, G1, BE1, W2, B2, G2, BE2, W3, B3,
        out, E, nNodes);
}